// round 16
// baseline (speedup 1.0000x reference)
#include <cuda_runtime.h>
#include <cuda_bf16.h>
#include <stdint.h>

// out[B=1024, W=201000] f32 one-hot triple scatter over zeros.
// Inputs: z f32 (unused), hID i32[1024], rID i32[1024], tID i32[1024].
//
// 148 CTAs (1/SM) x 1024 threads, each CTA streams a contiguous ~5.6MB slice
// sequentially (148 DRAM write streams instead of ~1200 interleaved bursts),
// with 8-deep v8-store unroll for MLP (R10 retried with 4x the warps).
// Scatter fused via per-thread chunk ownership.

#define ENTITIES_N  100000
#define RELATIONS_N 1000
#define WIDTH       201000
#define BATCH       1024
#define TOTAL_V8    25728000u        // 1024*201000/8
#define GRID        148
#define THREADS     1024
#define Q_V8        173838u          // ceil(TOTAL_V8/148)
#define UNROLL      8

__global__ void __launch_bounds__(THREADS) stream_onehot_fill(
    const int* __restrict__ hID,
    const int* __restrict__ rID,
    const int* __restrict__ tID,
    float* __restrict__ out)
{
    const unsigned start = blockIdx.x * Q_V8;
    const unsigned end   = min(start + Q_V8, TOTAL_V8);
    const unsigned tid   = threadIdx.x;

    // ---- Sequential streaming fill: 8 x st.global.v8 per iteration ----
    // Each iteration the CTA covers a contiguous 256KB window.
    unsigned i = start + tid;
    for (; i + (UNROLL - 1u) * THREADS < end; i += UNROLL * THREADS) {
#pragma unroll
        for (int k = 0; k < UNROLL; k++) {
            float* addr = out + (size_t)(i + k * THREADS) * 8;
            asm volatile(
                "st.global.v8.f32 [%0], {%1,%1,%1,%1,%1,%1,%1,%1};"
                :: "l"(addr), "f"(0.0f) : "memory");
        }
    }
    for (; i < end; i += THREADS) {
        float* addr = out + (size_t)i * 8;
        asm volatile(
            "st.global.v8.f32 [%0], {%1,%1,%1,%1,%1,%1,%1,%1};"
            :: "l"(addr), "f"(0.0f) : "memory");
    }

    // ---- Fused scatter: hot elements inside this CTA's slice ----
    // Thread t owns chunk c iff (c - start) % 1024 == t; its 1.0 store is
    // after its zero store in program order. Slice spans <= 9 rows.
    const unsigned lo   = start * 8u;
    const unsigned hi   = end * 8u;            // fits: max 205,824,000 < 2^31
    const unsigned row0 = lo / (unsigned)WIDTH;
    const unsigned row1 = (hi - 1u) / (unsigned)WIDTH;

    for (unsigned row = row0; row <= row1; row++) {
        const unsigned rbase = row * (unsigned)WIDTH;
        unsigned q[3];
        q[0] = rbase + (unsigned)__ldg(&hID[row]);
        q[1] = rbase + (unsigned)(ENTITIES_N + __ldg(&rID[row]));
        q[2] = rbase + (unsigned)(ENTITIES_N + RELATIONS_N + __ldg(&tID[row]));
#pragma unroll
        for (int j = 0; j < 3; j++) {
            const unsigned chunk = q[j] >> 3;
            if (chunk >= start && chunk < end &&
                ((chunk - start) & (THREADS - 1u)) == tid) {
                out[q[j]] = 1.0f;
            }
        }
    }
}

extern "C" void kernel_launch(void* const* d_in, const int* in_sizes, int n_in,
                              void* d_out, int out_size) {
    const int* hID = (const int*)d_in[1];
    const int* rID = (const int*)d_in[2];
    const int* tID = (const int*)d_in[3];
    stream_onehot_fill<<<GRID, THREADS>>>(hID, rID, tID, (float*)d_out);
}

// round 17
// speedup vs baseline: 1.2160x; 1.2160x over previous
#include <cuda_runtime.h>
#include <cuda_bf16.h>
#include <stdint.h>

// out[B=1024, W=201000] f32 one-hot triple scatter over zeros.
// Inputs: z f32 (unused), hID i32[1024], rID i32[1024], tID i32[1024].
//
// Fused fill+scatter (R5 layout: many CTAs, high occupancy — measured best
// SM-fill config at 87.9% DRAM), with st.global.cs (evict-first / streaming)
// so the L2 drains dirty lines eagerly instead of under capacity pressure.

#define ENTITIES_N  100000
#define RELATIONS_N 1000
#define WIDTH       201000          // floats per row
#define BATCH       1024
#define THREADS     512
#define V8_PER_THR  4               // 4 x 32B per thread
#define V8_PER_BLK  (THREADS * V8_PER_THR)          // 2048 v8 = 64 KB per block
// total v8 chunks = 1024*201000/8 = 25,728,000 = 12562.5 * 2048 -> use 12563
// blocks with tail guard? 25,728,000 / 2048 = 12562.5. Not exact; instead use
// grid so that work = blocks * 2048, guard the tail.
#define NBLOCKS     12563

__global__ void __launch_bounds__(THREADS) fused_onehot_fill_cs(
    const int* __restrict__ hID,
    const int* __restrict__ rID,
    const int* __restrict__ tID,
    float* __restrict__ out)
{
    const unsigned TOTAL_V8 = 25728000u;
    const unsigned base = blockIdx.x * (unsigned)V8_PER_BLK + threadIdx.x;

    // ---- Pure fill: 4 x st.global.cs.v8 of zeros (evict-first) ----
#pragma unroll
    for (int k = 0; k < V8_PER_THR; k++) {
        const unsigned idx = base + (unsigned)(k * THREADS);
        if (idx < TOTAL_V8) {
            float* addr = out + (size_t)idx * 8;
            asm volatile(
                "st.global.cs.v8.f32 [%0], {%1,%1,%1,%1,%1,%1,%1,%1};"
                :: "l"(addr), "f"(0.0f) : "memory");
        }
    }

    // ---- Once-per-thread epilogue: overwrite owned hot elements ----
    const unsigned W8 = WIDTH / 8u;      // 25125 v8 chunks per row (exact)
    const unsigned rowA = base / W8;
    unsigned lastIdx = base + (V8_PER_THR - 1) * THREADS;
    if (lastIdx >= TOTAL_V8) lastIdx = TOTAL_V8 - 1u;   // tail block clamp
    const unsigned rowB = lastIdx / W8;

#pragma unroll
    for (int which = 0; which < 2; which++) {
        const unsigned row = which ? rowB : rowA;
        if (which && rowB == rowA) break;
        if (row >= (unsigned)BATCH) break;

        const unsigned rbase = row * (unsigned)WIDTH;
        unsigned q[3];
        q[0] = rbase + (unsigned)__ldg(&hID[row]);
        q[1] = rbase + (unsigned)(ENTITIES_N + __ldg(&rID[row]));
        q[2] = rbase + (unsigned)(ENTITIES_N + RELATIONS_N + __ldg(&tID[row]));

#pragma unroll
        for (int j = 0; j < 3; j++) {
            const unsigned chunk = q[j] >> 3;          // owning 32B chunk
            const unsigned d     = chunk - base;       // unsigned wrap ok
            if (d < (unsigned)V8_PER_BLK && (d % (unsigned)THREADS) == 0u &&
                chunk < TOTAL_V8) {
                // Same thread wrote the zeros for this chunk (program order).
                out[q[j]] = 1.0f;
            }
        }
    }
}

extern "C" void kernel_launch(void* const* d_in, const int* in_sizes, int n_in,
                              void* d_out, int out_size) {
    const int* hID = (const int*)d_in[1];
    const int* rID = (const int*)d_in[2];
    const int* tID = (const int*)d_in[3];
    fused_onehot_fill_cs<<<NBLOCKS, THREADS>>>(hID, rID, tID, (float*)d_out);
}